// round 14
// baseline (speedup 1.0000x reference)
#include <cuda_runtime.h>
#include <cuda_fp16.h>
#include <cstdint>

#define Bq 32
#define Sq 48
#define Lq 64
#define Fq 256
#define NTILES (Bq * Sq)
#define GRID 152

// ---------------- staged W1 in mma.sync B-fragment layout (fp16) ----------------
__device__ __align__(16) uint4 g_Wf[16 * 16 * 32];   // 128KB

__device__ __forceinline__ uint32_t pack_h(float lo, float hi) {
    __half2 h = __floats2half2_rn(lo, hi);
    return *reinterpret_cast<uint32_t*>(&h);
}

__global__ void stage_w1_kernel(const float* __restrict__ W1) {
    int idx = blockIdx.x * 256 + threadIdx.x;   // 8192 uint4s
    int lane = idx & 31;
    int nbp  = (idx >> 5) & 15;
    int s    = idx >> 9;
    int g = lane >> 2, q = lane & 3;
    int k0 = s * 16 + q * 2;
    uint4 r;
    uint32_t* rr = reinterpret_cast<uint32_t*>(&r);
    #pragma unroll
    for (int h = 0; h < 2; ++h) {
        int col = (nbp * 2 + h) * 8 + g;
        rr[h * 2 + 0] = pack_h(W1[(k0 + 0) * 256 + col], W1[(k0 + 1) * 256 + col]);
        rr[h * 2 + 1] = pack_h(W1[(k0 + 8) * 256 + col], W1[(k0 + 9) * 256 + col]);
    }
    g_Wf[idx] = r;
}

// ---------------- helpers ----------------
__device__ __forceinline__ uint32_t smem_u32(const void* p) {
    uint32_t a;
    asm("{ .reg .u64 t; cvta.to.shared.u64 t, %1; cvt.u32.u64 %0, t; }" : "=r"(a) : "l"(p));
    return a;
}
__device__ __forceinline__ void cp16(uint32_t dst, const void* src) {
    asm volatile("cp.async.ca.shared.global [%0], [%1], 16;" :: "r"(dst), "l"(src));
}
#define CP_COMMIT()   asm volatile("cp.async.commit_group;" ::: "memory")
#define CP_WAIT_ALL() asm volatile("cp.async.wait_group 0;" ::: "memory")
#define CBAR() asm volatile("bar.sync 1, 256;" ::: "memory")
#define UBAR() asm volatile("bar.sync 2, 256;" ::: "memory")

__device__ __forceinline__ void mma16816(float* c, const uint4& a, uint32_t b0, uint32_t b1) {
    asm volatile(
        "mma.sync.aligned.m16n8k16.row.col.f32.f16.f16.f32 "
        "{%0,%1,%2,%3},{%4,%5,%6,%7},{%8,%9},{%0,%1,%2,%3};"
        : "+f"(c[0]), "+f"(c[1]), "+f"(c[2]), "+f"(c[3])
        : "r"(a.x), "r"(a.y), "r"(a.z), "r"(a.w), "r"(b0), "r"(b1));
}

// ---------------- SMEM layout (bytes) ----------------
static constexpr int WR_OFF   = 0;         // W ring: 4 slots x 8KB = 32KB
static constexpr int XF_OFF   = 32768;     // X A-fragments, 2 buffers x 64KB
static constexpr int PRED_OFF = 163840;    // float[256] (C epilogue)
static constexpr int P5_OFF   = 164864;    // float4[256] (U phase5 partials)
static constexpr int W2B1_OFF = 168960;    // float2[256]
static constexpr int SC_OFF   = 171008;    // float[64] x 2 buffers
static constexpr int WGT_OFF  = 171520;    // float[64]
static constexpr int SMEM_BYTES = 171776;

// convert one (b,s) tile of X (64x256 f32) into fp16 hi/lo A-fragment layout
__device__ __forceinline__ void convert_x(const float4* __restrict__ gx,
                                          char* __restrict__ xf,
                                          int tid, int stride, int iters) {
    #pragma unroll 4
    for (int r = 0; r < iters; ++r) {
        int idx = tid + r * stride;          // float4 index = m*64 + qq
        int m = idx >> 6, qq = idx & 63;
        float4 x = gx[idx];
        int s     = qq >> 2;
        int colk4 = qq & 3;
        int mtg   = m >> 4;
        int half  = (m >> 3) & 1;
        int regIdx = ((colk4 >> 1) << 1) + half;       // 0..3
        int lane0  = (m & 7) * 4 + (colk4 & 1) * 2;
        uint32_t off_h = (((s * 8) + mtg) * 32 + lane0) * 16 + regIdx * 4;
        uint32_t off_l = off_h + 2048;
        __half2 h0 = __floats2half2_rn(x.x, x.y);
        __half2 h1 = __floats2half2_rn(x.z, x.w);
        float2 f0 = __half22float2(h0);
        float2 f1 = __half22float2(h1);
        __half2 l0 = __floats2half2_rn(x.x - f0.x, x.y - f0.y);
        __half2 l1 = __floats2half2_rn(x.z - f1.x, x.w - f1.y);
        *reinterpret_cast<uint32_t*>(xf + off_h)      = *reinterpret_cast<uint32_t*>(&h0);
        *reinterpret_cast<uint32_t*>(xf + off_h + 16) = *reinterpret_cast<uint32_t*>(&h1);
        *reinterpret_cast<uint32_t*>(xf + off_l)      = *reinterpret_cast<uint32_t*>(&l0);
        *reinterpret_cast<uint32_t*>(xf + off_l + 16) = *reinterpret_cast<uint32_t*>(&l1);
    }
}

__global__ __launch_bounds__(512, 1)
void ida_ws_kernel(const float* __restrict__ features,
                   const float* __restrict__ src_locs,
                   const float* __restrict__ tar_locs,
                   const float* __restrict__ b1,
                   const float* __restrict__ W2,
                   const float* __restrict__ b2,
                   float* __restrict__ out)
{
    extern __shared__ char smem[];
    const uint32_t sb = smem_u32(smem);
    const int t    = threadIdx.x;
    const int lane = t & 31;
    const int wid  = t >> 5;
    const int bid  = blockIdx.x;
    const int T    = (NTILES - 1 - bid) / GRID + 1;   // tiles for this CTA

    // ---- prologue: aux + convert tile 0 (all 512 threads) ----
    if (t < 256) {
        float2* wb = reinterpret_cast<float2*>(smem + W2B1_OFF);
        wb[t] = make_float2(b1[t], W2[t]);
    }
    const float b2v = b2[0];
    convert_x(reinterpret_cast<const float4*>(features + (size_t)bid * (Lq * Fq)),
              smem + XF_OFF, t, 512, 8);
    __syncthreads();

    #pragma unroll 1
    for (int it = 0; it <= T; ++it) {
        __syncthreads();     // cross-group handoff: Xf[it&1] ready, sc[(it-1)&1] ready

        if (t < 256) {
            // ================= C-group: GEMM + epilogue for tile it =================
            if (it < T) {
                const int bs = bid + it * GRID;
                const int b  = bs / Sq;
                const int warp_m = wid & 1;
                const int warp_n = wid >> 1;      // 0..3
                const int g = lane >> 2, q = lane & 3;

                // W ring prologue: stages 0,1
                #pragma unroll
                for (int p = 0; p < 2; ++p) {
                    #pragma unroll
                    for (int j = 0; j < 2; ++j) {
                        int seg = t + j * 256;
                        cp16(sb + WR_OFF + p * 8192 + seg * 16, g_Wf + p * 512 + seg);
                    }
                    CP_COMMIT();
                }
                // invd in registers (latency hidden under cp.async waits)
                float invd_reg = 0.f;
                if (t < Lq) {
                    float dx = src_locs[(b * Lq + t) * 2 + 0] - tar_locs[b * 2 + 0];
                    float dy = src_locs[(b * Lq + t) * 2 + 1] - tar_locs[b * 2 + 1];
                    invd_reg = rsqrtf(dx * dx + dy * dy);
                }

                const char* xfc = smem + XF_OFF + (it & 1) * 65536;
                float acc[2][8][4];
                #pragma unroll
                for (int mt = 0; mt < 2; ++mt)
                    #pragma unroll
                    for (int nt = 0; nt < 8; ++nt)
                        #pragma unroll
                        for (int k = 0; k < 4; ++k) acc[mt][nt][k] = 0.f;

                #pragma unroll 1
                for (int itk = 0; itk < 8; ++itk) {
                    const int s0 = itk * 2;
                    CP_WAIT_ALL();
                    CBAR();
                    if (itk < 7) {
                        #pragma unroll
                        for (int p = 0; p < 2; ++p) {
                            int stg = s0 + 2 + p;
                            uint32_t dstb = sb + WR_OFF + (stg & 3) * 8192;
                            const uint4* srcb = g_Wf + stg * 512;
                            #pragma unroll
                            for (int j = 0; j < 2; ++j) {
                                int seg = t + j * 256;
                                cp16(dstb + seg * 16, srcb + seg);
                            }
                            CP_COMMIT();
                        }
                    }
                    const char* st0 = smem + WR_OFF + ((s0 + 0) & 3) * 8192;
                    const char* st1 = smem + WR_OFF + ((s0 + 1) & 3) * 8192;
                    const char* xf0 = xfc + s0 * 4096;
                    const char* xf1 = xf0 + 4096;

                    uint4 A0h[2], A0l[2], A1h[2], A1l[2];
                    #pragma unroll
                    for (int mt = 0; mt < 2; ++mt) {
                        int mtg = warp_m * 2 + mt;
                        A0h[mt] = *reinterpret_cast<const uint4*>(xf0 + (mtg * 32 + lane) * 16);
                        A0l[mt] = *reinterpret_cast<const uint4*>(xf0 + 2048 + (mtg * 32 + lane) * 16);
                        A1h[mt] = *reinterpret_cast<const uint4*>(xf1 + (mtg * 32 + lane) * 16);
                        A1l[mt] = *reinterpret_cast<const uint4*>(xf1 + 2048 + (mtg * 32 + lane) * 16);
                    }
                    #pragma unroll
                    for (int i = 0; i < 4; ++i) {
                        uint4 B = *reinterpret_cast<const uint4*>(st0 + ((warp_n * 4 + i) * 32 + lane) * 16);
                        mma16816(acc[0][i * 2 + 0], A0h[0], B.x, B.y);
                        mma16816(acc[1][i * 2 + 0], A0h[1], B.x, B.y);
                        mma16816(acc[0][i * 2 + 1], A0h[0], B.z, B.w);
                        mma16816(acc[1][i * 2 + 1], A0h[1], B.z, B.w);
                        mma16816(acc[0][i * 2 + 0], A0l[0], B.x, B.y);
                        mma16816(acc[1][i * 2 + 0], A0l[1], B.x, B.y);
                        mma16816(acc[0][i * 2 + 1], A0l[0], B.z, B.w);
                        mma16816(acc[1][i * 2 + 1], A0l[1], B.z, B.w);
                    }
                    #pragma unroll
                    for (int i = 0; i < 4; ++i) {
                        uint4 B = *reinterpret_cast<const uint4*>(st1 + ((warp_n * 4 + i) * 32 + lane) * 16);
                        mma16816(acc[0][i * 2 + 0], A1h[0], B.x, B.y);
                        mma16816(acc[1][i * 2 + 0], A1h[1], B.x, B.y);
                        mma16816(acc[0][i * 2 + 1], A1h[0], B.z, B.w);
                        mma16816(acc[1][i * 2 + 1], A1h[1], B.z, B.w);
                        mma16816(acc[0][i * 2 + 0], A1l[0], B.x, B.y);
                        mma16816(acc[1][i * 2 + 0], A1l[1], B.x, B.y);
                        mma16816(acc[0][i * 2 + 1], A1l[0], B.z, B.w);
                        mma16816(acc[1][i * 2 + 1], A1l[1], B.z, B.w);
                    }
                }

                // epilogue: p = sum_col relu(D+b1)*W2, quad-reduce
                {
                    const float2* wb = reinterpret_cast<const float2*>(smem + W2B1_OFF);
                    float* pred = reinterpret_cast<float*>(smem + PRED_OFF);
                    #pragma unroll
                    for (int mt = 0; mt < 2; ++mt) {
                        float p0 = 0.f, p1 = 0.f;
                        #pragma unroll
                        for (int nt = 0; nt < 8; ++nt) {
                            int col0 = warp_n * 64 + nt * 8 + q * 2;
                            float2 c0 = wb[col0];
                            float2 c1 = wb[col0 + 1];
                            const float* c = acc[mt][nt];
                            p0 = fmaf(fmaxf(c[0] + c0.x, 0.f), c0.y, p0);
                            p0 = fmaf(fmaxf(c[1] + c1.x, 0.f), c1.y, p0);
                            p1 = fmaf(fmaxf(c[2] + c0.x, 0.f), c0.y, p1);
                            p1 = fmaf(fmaxf(c[3] + c1.x, 0.f), c1.y, p1);
                        }
                        #pragma unroll
                        for (int off = 1; off < 4; off <<= 1) {
                            p0 += __shfl_xor_sync(0xffffffffu, p0, off);
                            p1 += __shfl_xor_sync(0xffffffffu, p1, off);
                        }
                        if (q == 0) {
                            int row = warp_m * 32 + mt * 16 + g;
                            pred[warp_n * 64 + row]     = p0;
                            pred[warp_n * 64 + row + 8] = p1;
                        }
                    }
                    CBAR();
                    if (t < 64) {
                        const float* pr = reinterpret_cast<const float*>(smem + PRED_OFF);
                        float ptot = pr[t] + pr[t + 64] + pr[t + 128] + pr[t + 192];
                        float sscore = fmaxf(ptot + b2v, 0.f) * invd_reg;
                        reinterpret_cast<float*>(smem + SC_OFF + (it & 1) * 256)[t] = sscore;
                    }
                }
            }
        } else {
            // ================= U-group: convert(it+1), softmax+phase5(it-1) =================
            const int ut = t - 256;
            if (it + 1 < T) {
                const int bsn = bid + (it + 1) * GRID;
                convert_x(reinterpret_cast<const float4*>(features + (size_t)bsn * (Lq * Fq)),
                          smem + XF_OFF + ((it + 1) & 1) * 65536, ut, 256, 16);
            }
            if (it >= 1) {
                const int bsp = bid + (it - 1) * GRID;
                // softmax over L=64 (first U warp)
                if (wid == 8) {
                    const float* sc = reinterpret_cast<const float*>(smem + SC_OFF + ((it - 1) & 1) * 256);
                    float* wg = reinterpret_cast<float*>(smem + WGT_OFF);
                    float s0 = sc[lane], s1 = sc[lane + 32];
                    float m = fmaxf(s0, s1);
                    #pragma unroll
                    for (int off = 16; off > 0; off >>= 1)
                        m = fmaxf(m, __shfl_xor_sync(0xffffffffu, m, off));
                    float e0 = expf(s0 - m), e1 = expf(s1 - m);
                    float ssum = e0 + e1;
                    #pragma unroll
                    for (int off = 16; off > 0; off >>= 1)
                        ssum += __shfl_xor_sync(0xffffffffu, ssum, off);
                    float inv = 1.f / ssum;
                    wg[lane] = e0 * inv;
                    wg[lane + 32] = e1 * inv;
                }
                UBAR();
                // phase 5: out[bsp,:] = sum_l wgt[l] * features[bsp,l,:]
                {
                    const float* wg = reinterpret_cast<const float*>(smem + WGT_OFF);
                    const float4* fx = reinterpret_cast<const float4*>(features + (size_t)bsp * (Lq * Fq));
                    float4* p54 = reinterpret_cast<float4*>(smem + P5_OFF);
                    const int fb  = ut & 63;
                    const int sub = ut >> 6;      // 0..3 -> l in [sub*16, +16)
                    float4 o = make_float4(0.f, 0.f, 0.f, 0.f);
                    #pragma unroll 4
                    for (int i = 0; i < 16; ++i) {
                        int l = sub * 16 + i;
                        float w = wg[l];
                        float4 x = fx[l * 64 + fb];
                        o.x = fmaf(w, x.x, o.x);
                        o.y = fmaf(w, x.y, o.y);
                        o.z = fmaf(w, x.z, o.z);
                        o.w = fmaf(w, x.w, o.w);
                    }
                    p54[ut] = o;
                    UBAR();
                    if (ut < 64) {
                        float4 a0 = p54[ut], a1 = p54[ut + 64], a2 = p54[ut + 128], a3 = p54[ut + 192];
                        float4 o2;
                        o2.x = a0.x + a1.x + a2.x + a3.x;
                        o2.y = a0.y + a1.y + a2.y + a3.y;
                        o2.z = a0.z + a1.z + a2.z + a3.z;
                        o2.w = a0.w + a1.w + a2.w + a3.w;
                        reinterpret_cast<float4*>(out + (size_t)bsp * Fq)[ut] = o2;
                    }
                }
            }
        }
    }
}

extern "C" void kernel_launch(void* const* d_in, const int* in_sizes, int n_in,
                              void* d_out, int out_size)
{
    const float* features = (const float*)d_in[0];
    const float* src_locs = (const float*)d_in[1];
    const float* tar_locs = (const float*)d_in[2];
    const float* W1       = (const float*)d_in[3];
    const float* b1       = (const float*)d_in[4];
    const float* W2       = (const float*)d_in[5];
    const float* b2       = (const float*)d_in[6];
    float* out            = (float*)d_out;

    stage_w1_kernel<<<32, 256>>>(W1);

    cudaFuncSetAttribute(ida_ws_kernel,
                         cudaFuncAttributeMaxDynamicSharedMemorySize, SMEM_BYTES);
    ida_ws_kernel<<<GRID, 512, SMEM_BYTES>>>(
        features, src_locs, tar_locs, b1, W2, b2, out);
}

// round 15
// speedup vs baseline: 1.4378x; 1.4378x over previous
#include <cuda_runtime.h>
#include <cuda_fp16.h>
#include <cstdint>

#define Bq 32
#define Sq 48
#define Lq 64
#define Fq 256
#define NTILES (Bq * Sq)
#define GRID 152

// ---------------- staged W1 in mma.sync B-fragment layout (fp16) ----------------
__device__ __align__(16) uint4 g_Wf[16 * 16 * 32];   // 128KB

__device__ __forceinline__ uint32_t pack_h(float lo, float hi) {
    __half2 h = __floats2half2_rn(lo, hi);
    return *reinterpret_cast<uint32_t*>(&h);
}

__global__ void stage_w1_kernel(const float* __restrict__ W1) {
    int idx = blockIdx.x * 256 + threadIdx.x;   // 8192 uint4s
    int lane = idx & 31;
    int nbp  = (idx >> 5) & 15;
    int s    = idx >> 9;
    int g = lane >> 2, q = lane & 3;
    int k0 = s * 16 + q * 2;
    uint4 r;
    uint32_t* rr = reinterpret_cast<uint32_t*>(&r);
    #pragma unroll
    for (int h = 0; h < 2; ++h) {
        int col = (nbp * 2 + h) * 8 + g;
        rr[h * 2 + 0] = pack_h(W1[(k0 + 0) * 256 + col], W1[(k0 + 1) * 256 + col]);
        rr[h * 2 + 1] = pack_h(W1[(k0 + 8) * 256 + col], W1[(k0 + 9) * 256 + col]);
    }
    g_Wf[idx] = r;
}

// ---------------- helpers ----------------
__device__ __forceinline__ uint32_t smem_u32(const void* p) {
    uint32_t a;
    asm("{ .reg .u64 t; cvta.to.shared.u64 t, %1; cvt.u32.u64 %0, t; }" : "=r"(a) : "l"(p));
    return a;
}
__device__ __forceinline__ void cp16(uint32_t dst, const void* src) {
    asm volatile("cp.async.ca.shared.global [%0], [%1], 16;" :: "r"(dst), "l"(src));
}
#define CP_COMMIT()   asm volatile("cp.async.commit_group;" ::: "memory")
#define CP_WAIT_ALL() asm volatile("cp.async.wait_group 0;" ::: "memory")
#define CBAR() asm volatile("bar.sync 1, 256;" ::: "memory")
#define UBAR() asm volatile("bar.sync 2, 256;" ::: "memory")

__device__ __forceinline__ void mma16816(float* c, const uint4& a, uint32_t b0, uint32_t b1) {
    asm volatile(
        "mma.sync.aligned.m16n8k16.row.col.f32.f16.f16.f32 "
        "{%0,%1,%2,%3},{%4,%5,%6,%7},{%8,%9},{%0,%1,%2,%3};"
        : "+f"(c[0]), "+f"(c[1]), "+f"(c[2]), "+f"(c[3])
        : "r"(a.x), "r"(a.y), "r"(a.z), "r"(a.w), "r"(b0), "r"(b1));
}

// ---------------- SMEM layout (bytes) ----------------
static constexpr int WR_OFF   = 0;         // W ring: 4 slots x 8KB = 32KB
static constexpr int XF_OFF   = 32768;     // X A-fragments (hi only), 2 buffers x 32KB
static constexpr int PRED_OFF = 98304;     // float[256]
static constexpr int P5_OFF   = 99328;     // float4[256] = 4KB
static constexpr int W2B1_OFF = 103424;    // float2[256] = 2KB
static constexpr int SC_OFF   = 105472;    // float[64] x 2 buffers = 512B
static constexpr int WGT_OFF  = 105984;    // float[64]
static constexpr int SMEM_BYTES = 106240;

// convert one (b,s) tile of X (64x256 f32) into fp16 A-fragment layout (single term)
// layout: [s 16][mtg 4][lane 32] uint4 -> s*2048 + mtg*512 + lane*16 bytes
__device__ __forceinline__ void convert_x(const float4* __restrict__ gx,
                                          char* __restrict__ xf,
                                          int tid, int stride, int iters) {
    #pragma unroll 4
    for (int r = 0; r < iters; ++r) {
        int idx = tid + r * stride;          // float4 index = m*64 + qq
        int m = idx >> 6, qq = idx & 63;
        float4 x = gx[idx];
        int s     = qq >> 2;
        int colk4 = qq & 3;
        int mtg   = m >> 4;
        int half  = (m >> 3) & 1;
        int regIdx = ((colk4 >> 1) << 1) + half;       // 0..3
        int lane0  = (m & 7) * 4 + (colk4 & 1) * 2;
        uint32_t off_h = ((s * 4 + mtg) * 32 + lane0) * 16 + regIdx * 4;
        __half2 h0 = __floats2half2_rn(x.x, x.y);
        __half2 h1 = __floats2half2_rn(x.z, x.w);
        *reinterpret_cast<uint32_t*>(xf + off_h)      = *reinterpret_cast<uint32_t*>(&h0);
        *reinterpret_cast<uint32_t*>(xf + off_h + 16) = *reinterpret_cast<uint32_t*>(&h1);
    }
}

__global__ __launch_bounds__(512, 1)
void ida_ws_kernel(const float* __restrict__ features,
                   const float* __restrict__ src_locs,
                   const float* __restrict__ tar_locs,
                   const float* __restrict__ b1,
                   const float* __restrict__ W2,
                   const float* __restrict__ b2,
                   float* __restrict__ out)
{
    extern __shared__ char smem[];
    const uint32_t sb = smem_u32(smem);
    const int t    = threadIdx.x;
    const int lane = t & 31;
    const int wid  = t >> 5;
    const int bid  = blockIdx.x;
    const int T    = (NTILES - 1 - bid) / GRID + 1;   // tiles for this CTA

    // ---- prologue: aux + convert tile 0 (all 512 threads) ----
    if (t < 256) {
        float2* wb = reinterpret_cast<float2*>(smem + W2B1_OFF);
        wb[t] = make_float2(b1[t], W2[t]);
    }
    const float b2v = b2[0];
    convert_x(reinterpret_cast<const float4*>(features + (size_t)bid * (Lq * Fq)),
              smem + XF_OFF, t, 512, 8);
    __syncthreads();

    #pragma unroll 1
    for (int it = 0; it <= T; ++it) {
        __syncthreads();     // handoff: Xf[it&1] ready, sc[(it-1)&1] ready

        if (t < 256) {
            // ================= C-group: GEMM + epilogue for tile it =================
            if (it < T) {
                const int bs = bid + it * GRID;
                const int b  = bs / Sq;
                const int warp_m = wid & 1;
                const int warp_n = wid >> 1;      // 0..3
                const int g = lane >> 2, q = lane & 3;

                // W ring prologue: stages 0,1
                #pragma unroll
                for (int p = 0; p < 2; ++p) {
                    #pragma unroll
                    for (int j = 0; j < 2; ++j) {
                        int seg = t + j * 256;
                        cp16(sb + WR_OFF + p * 8192 + seg * 16, g_Wf + p * 512 + seg);
                    }
                    CP_COMMIT();
                }
                float invd_reg = 0.f;
                if (t < Lq) {
                    float dx = src_locs[(b * Lq + t) * 2 + 0] - tar_locs[b * 2 + 0];
                    float dy = src_locs[(b * Lq + t) * 2 + 1] - tar_locs[b * 2 + 1];
                    invd_reg = rsqrtf(dx * dx + dy * dy);
                }

                const char* xfc = smem + XF_OFF + (it & 1) * 32768;
                float acc[2][8][4];
                #pragma unroll
                for (int mt = 0; mt < 2; ++mt)
                    #pragma unroll
                    for (int nt = 0; nt < 8; ++nt)
                        #pragma unroll
                        for (int k = 0; k < 4; ++k) acc[mt][nt][k] = 0.f;

                #pragma unroll 1
                for (int itk = 0; itk < 8; ++itk) {
                    const int s0 = itk * 2;
                    CP_WAIT_ALL();
                    CBAR();
                    if (itk < 7) {
                        #pragma unroll
                        for (int p = 0; p < 2; ++p) {
                            int stg = s0 + 2 + p;
                            uint32_t dstb = sb + WR_OFF + (stg & 3) * 8192;
                            const uint4* srcb = g_Wf + stg * 512;
                            #pragma unroll
                            for (int j = 0; j < 2; ++j) {
                                int seg = t + j * 256;
                                cp16(dstb + seg * 16, srcb + seg);
                            }
                            CP_COMMIT();
                        }
                    }
                    const char* st0 = smem + WR_OFF + ((s0 + 0) & 3) * 8192;
                    const char* st1 = smem + WR_OFF + ((s0 + 1) & 3) * 8192;
                    const char* xf0 = xfc + s0 * 2048;
                    const char* xf1 = xf0 + 2048;

                    uint4 A0[2], A1[2];
                    #pragma unroll
                    for (int mt = 0; mt < 2; ++mt) {
                        int mtg = warp_m * 2 + mt;
                        A0[mt] = *reinterpret_cast<const uint4*>(xf0 + (mtg * 32 + lane) * 16);
                        A1[mt] = *reinterpret_cast<const uint4*>(xf1 + (mtg * 32 + lane) * 16);
                    }
                    #pragma unroll
                    for (int i = 0; i < 4; ++i) {
                        uint4 B = *reinterpret_cast<const uint4*>(st0 + ((warp_n * 4 + i) * 32 + lane) * 16);
                        mma16816(acc[0][i * 2 + 0], A0[0], B.x, B.y);
                        mma16816(acc[1][i * 2 + 0], A0[1], B.x, B.y);
                        mma16816(acc[0][i * 2 + 1], A0[0], B.z, B.w);
                        mma16816(acc[1][i * 2 + 1], A0[1], B.z, B.w);
                    }
                    #pragma unroll
                    for (int i = 0; i < 4; ++i) {
                        uint4 B = *reinterpret_cast<const uint4*>(st1 + ((warp_n * 4 + i) * 32 + lane) * 16);
                        mma16816(acc[0][i * 2 + 0], A1[0], B.x, B.y);
                        mma16816(acc[1][i * 2 + 0], A1[1], B.x, B.y);
                        mma16816(acc[0][i * 2 + 1], A1[0], B.z, B.w);
                        mma16816(acc[1][i * 2 + 1], A1[1], B.z, B.w);
                    }
                }

                // epilogue: p = sum_col relu(D+b1)*W2, quad-reduce
                {
                    const float2* wb = reinterpret_cast<const float2*>(smem + W2B1_OFF);
                    float* pred = reinterpret_cast<float*>(smem + PRED_OFF);
                    #pragma unroll
                    for (int mt = 0; mt < 2; ++mt) {
                        float p0 = 0.f, p1 = 0.f;
                        #pragma unroll
                        for (int nt = 0; nt < 8; ++nt) {
                            int col0 = warp_n * 64 + nt * 8 + q * 2;
                            float2 c0 = wb[col0];
                            float2 c1 = wb[col0 + 1];
                            const float* c = acc[mt][nt];
                            p0 = fmaf(fmaxf(c[0] + c0.x, 0.f), c0.y, p0);
                            p0 = fmaf(fmaxf(c[1] + c1.x, 0.f), c1.y, p0);
                            p1 = fmaf(fmaxf(c[2] + c0.x, 0.f), c0.y, p1);
                            p1 = fmaf(fmaxf(c[3] + c1.x, 0.f), c1.y, p1);
                        }
                        #pragma unroll
                        for (int off = 1; off < 4; off <<= 1) {
                            p0 += __shfl_xor_sync(0xffffffffu, p0, off);
                            p1 += __shfl_xor_sync(0xffffffffu, p1, off);
                        }
                        if (q == 0) {
                            int row = warp_m * 32 + mt * 16 + g;
                            pred[warp_n * 64 + row]     = p0;
                            pred[warp_n * 64 + row + 8] = p1;
                        }
                    }
                    CBAR();
                    if (t < 64) {
                        const float* pr = reinterpret_cast<const float*>(smem + PRED_OFF);
                        float ptot = pr[t] + pr[t + 64] + pr[t + 128] + pr[t + 192];
                        float sscore = fmaxf(ptot + b2v, 0.f) * invd_reg;
                        reinterpret_cast<float*>(smem + SC_OFF + (it & 1) * 256)[t] = sscore;
                    }
                }
            }
        } else {
            // ================= U-group: convert(it+1), softmax+phase5(it-1) =================
            const int ut = t - 256;
            if (it + 1 < T) {
                const int bsn = bid + (it + 1) * GRID;
                convert_x(reinterpret_cast<const float4*>(features + (size_t)bsn * (Lq * Fq)),
                          smem + XF_OFF + ((it + 1) & 1) * 32768, ut, 256, 16);
            }
            if (it >= 1) {
                const int bsp = bid + (it - 1) * GRID;
                if (wid == 8) {
                    const float* sc = reinterpret_cast<const float*>(smem + SC_OFF + ((it - 1) & 1) * 256);
                    float* wg = reinterpret_cast<float*>(smem + WGT_OFF);
                    float s0 = sc[lane], s1 = sc[lane + 32];
                    float m = fmaxf(s0, s1);
                    #pragma unroll
                    for (int off = 16; off > 0; off >>= 1)
                        m = fmaxf(m, __shfl_xor_sync(0xffffffffu, m, off));
                    float e0 = expf(s0 - m), e1 = expf(s1 - m);
                    float ssum = e0 + e1;
                    #pragma unroll
                    for (int off = 16; off > 0; off >>= 1)
                        ssum += __shfl_xor_sync(0xffffffffu, ssum, off);
                    float inv = 1.f / ssum;
                    wg[lane] = e0 * inv;
                    wg[lane + 32] = e1 * inv;
                }
                UBAR();
                {
                    const float* wg = reinterpret_cast<const float*>(smem + WGT_OFF);
                    const float4* fx = reinterpret_cast<const float4*>(features + (size_t)bsp * (Lq * Fq));
                    float4* p54 = reinterpret_cast<float4*>(smem + P5_OFF);
                    const int fb  = ut & 63;
                    const int sub = ut >> 6;      // 0..3 -> l in [sub*16, +16)
                    float4 o = make_float4(0.f, 0.f, 0.f, 0.f);
                    #pragma unroll 4
                    for (int i = 0; i < 16; ++i) {
                        int l = sub * 16 + i;
                        float w = wg[l];
                        float4 x = fx[l * 64 + fb];
                        o.x = fmaf(w, x.x, o.x);
                        o.y = fmaf(w, x.y, o.y);
                        o.z = fmaf(w, x.z, o.z);
                        o.w = fmaf(w, x.w, o.w);
                    }
                    p54[ut] = o;
                    UBAR();
                    if (ut < 64) {
                        float4 a0 = p54[ut], a1 = p54[ut + 64], a2 = p54[ut + 128], a3 = p54[ut + 192];
                        float4 o2;
                        o2.x = a0.x + a1.x + a2.x + a3.x;
                        o2.y = a0.y + a1.y + a2.y + a3.y;
                        o2.z = a0.z + a1.z + a2.z + a3.z;
                        o2.w = a0.w + a1.w + a2.w + a3.w;
                        reinterpret_cast<float4*>(out + (size_t)bsp * Fq)[ut] = o2;
                    }
                }
            }
        }
    }
}

extern "C" void kernel_launch(void* const* d_in, const int* in_sizes, int n_in,
                              void* d_out, int out_size)
{
    const float* features = (const float*)d_in[0];
    const float* src_locs = (const float*)d_in[1];
    const float* tar_locs = (const float*)d_in[2];
    const float* W1       = (const float*)d_in[3];
    const float* b1       = (const float*)d_in[4];
    const float* W2       = (const float*)d_in[5];
    const float* b2       = (const float*)d_in[6];
    float* out            = (float*)d_out;

    stage_w1_kernel<<<32, 256>>>(W1);

    cudaFuncSetAttribute(ida_ws_kernel,
                         cudaFuncAttributeMaxDynamicSharedMemorySize, SMEM_BYTES);
    ida_ws_kernel<<<GRID, 512, SMEM_BYTES>>>(
        features, src_locs, tar_locs, b1, W2, b2, out);
}

// round 16
// speedup vs baseline: 1.7711x; 1.2318x over previous
#include <cuda_runtime.h>
#include <cuda_fp16.h>
#include <cstdint>

#define Bq 32
#define Sq 48
#define Lq 64
#define Fq 256
#define NTILES (Bq * Sq)
#define GRID 152

// ---------------- staged W1 in mma.sync B-fragment layout (fp16) ----------------
__device__ __align__(16) uint4 g_Wf[16 * 16 * 32];   // 128KB

__device__ __forceinline__ uint32_t pack_h(float lo, float hi) {
    __half2 h = __floats2half2_rn(lo, hi);
    return *reinterpret_cast<uint32_t*>(&h);
}

__global__ void stage_w1_kernel(const float* __restrict__ W1) {
    int idx = blockIdx.x * 256 + threadIdx.x;   // 8192 uint4s
    int lane = idx & 31;
    int nbp  = (idx >> 5) & 15;
    int s    = idx >> 9;
    int g = lane >> 2, q = lane & 3;
    int k0 = s * 16 + q * 2;
    uint4 r;
    uint32_t* rr = reinterpret_cast<uint32_t*>(&r);
    #pragma unroll
    for (int h = 0; h < 2; ++h) {
        int col = (nbp * 2 + h) * 8 + g;
        rr[h * 2 + 0] = pack_h(W1[(k0 + 0) * 256 + col], W1[(k0 + 1) * 256 + col]);
        rr[h * 2 + 1] = pack_h(W1[(k0 + 8) * 256 + col], W1[(k0 + 9) * 256 + col]);
    }
    g_Wf[idx] = r;
}

// ---------------- helpers ----------------
__device__ __forceinline__ uint32_t smem_u32(const void* p) {
    uint32_t a;
    asm("{ .reg .u64 t; cvta.to.shared.u64 t, %1; cvt.u32.u64 %0, t; }" : "=r"(a) : "l"(p));
    return a;
}
__device__ __forceinline__ void cp16(uint32_t dst, const void* src) {
    asm volatile("cp.async.ca.shared.global [%0], [%1], 16;" :: "r"(dst), "l"(src));
}
#define CP_COMMIT()   asm volatile("cp.async.commit_group;" ::: "memory")
#define CP_WAIT_ALL() asm volatile("cp.async.wait_group 0;" ::: "memory")
#define CBAR() asm volatile("bar.sync 1, 256;" ::: "memory")
#define UBAR() asm volatile("bar.sync 2, 256;" ::: "memory")

__device__ __forceinline__ void mma16816(float* c, const uint4& a, uint32_t b0, uint32_t b1) {
    asm volatile(
        "mma.sync.aligned.m16n8k16.row.col.f32.f16.f16.f32 "
        "{%0,%1,%2,%3},{%4,%5,%6,%7},{%8,%9},{%0,%1,%2,%3};"
        : "+f"(c[0]), "+f"(c[1]), "+f"(c[2]), "+f"(c[3])
        : "r"(a.x), "r"(a.y), "r"(a.z), "r"(a.w), "r"(b0), "r"(b1));
}

// ---------------- SMEM layout (bytes) ----------------
static constexpr int WF_OFF   = 0;         // resident W1 fragments: 16 x 8KB = 128KB
static constexpr int XF_OFF   = 131072;    // X A-fragments (single term), 2 buffers x 32KB
static constexpr int PRED_OFF = 196608;    // float[256] = 1KB
static constexpr int P5_OFF   = 197632;    // float4[256] = 4KB
static constexpr int W2B1_OFF = 201728;    // float2[256] = 2KB
static constexpr int SC_OFF   = 203776;    // float[64] x 2 buffers = 512B
static constexpr int WGT_OFF  = 204288;    // float[64]
static constexpr int SMEM_BYTES = 204544;

// convert one (b,s) tile of X (64x256 f32) into fp16 A-fragment layout (single term)
// layout: [s 16][mtg 4][lane 32] uint4 -> s*2048 + mtg*512 + lane*16 bytes
__device__ __forceinline__ void convert_x(const float4* __restrict__ gx,
                                          char* __restrict__ xf,
                                          int tid, int stride, int iters) {
    #pragma unroll 4
    for (int r = 0; r < iters; ++r) {
        int idx = tid + r * stride;          // float4 index = m*64 + qq
        int m = idx >> 6, qq = idx & 63;
        float4 x = gx[idx];
        int s     = qq >> 2;
        int colk4 = qq & 3;
        int mtg   = m >> 4;
        int half  = (m >> 3) & 1;
        int regIdx = ((colk4 >> 1) << 1) + half;       // 0..3
        int lane0  = (m & 7) * 4 + (colk4 & 1) * 2;
        uint32_t off_h = ((s * 4 + mtg) * 32 + lane0) * 16 + regIdx * 4;
        __half2 h0 = __floats2half2_rn(x.x, x.y);
        __half2 h1 = __floats2half2_rn(x.z, x.w);
        *reinterpret_cast<uint32_t*>(xf + off_h)      = *reinterpret_cast<uint32_t*>(&h0);
        *reinterpret_cast<uint32_t*>(xf + off_h + 16) = *reinterpret_cast<uint32_t*>(&h1);
    }
}

__global__ __launch_bounds__(512, 1)
void ida_ws_kernel(const float* __restrict__ features,
                   const float* __restrict__ src_locs,
                   const float* __restrict__ tar_locs,
                   const float* __restrict__ b1,
                   const float* __restrict__ W2,
                   const float* __restrict__ b2,
                   float* __restrict__ out)
{
    extern __shared__ char smem[];
    const uint32_t sb = smem_u32(smem);
    const int t    = threadIdx.x;
    const int lane = t & 31;
    const int wid  = t >> 5;
    const int bid  = blockIdx.x;
    const int T    = (NTILES - 1 - bid) / GRID + 1;   // tiles for this CTA

    // ---- one-time prologue: resident W1 (128KB) + aux + convert tile 0 ----
    {
        #pragma unroll
        for (int j = 0; j < 16; ++j) {
            int seg = t + j * 512;               // 8192 uint4s
            cp16(sb + WF_OFF + seg * 16, g_Wf + seg);
        }
        CP_COMMIT();
    }
    if (t < 256) {
        float2* wb = reinterpret_cast<float2*>(smem + W2B1_OFF);
        wb[t] = make_float2(b1[t], W2[t]);
    }
    const float b2v = b2[0];
    convert_x(reinterpret_cast<const float4*>(features + (size_t)bid * (Lq * Fq)),
              smem + XF_OFF, t, 512, 8);
    CP_WAIT_ALL();
    __syncthreads();

    #pragma unroll 1
    for (int it = 0; it <= T; ++it) {
        __syncthreads();     // handoff: Xf[it&1] ready, sc[(it-1)&1] ready

        if (t < 256) {
            // ================= C-group: GEMM + epilogue for tile it =================
            if (it < T) {
                const int bs = bid + it * GRID;
                const int b  = bs / Sq;
                const int warp_m = wid & 1;
                const int warp_n = wid >> 1;      // 0..3
                const int g = lane >> 2, q = lane & 3;

                float invd_reg = 0.f;
                if (t < Lq) {
                    float dx = src_locs[(b * Lq + t) * 2 + 0] - tar_locs[b * 2 + 0];
                    float dy = src_locs[(b * Lq + t) * 2 + 1] - tar_locs[b * 2 + 1];
                    invd_reg = rsqrtf(dx * dx + dy * dy);
                }

                const char* xfc = smem + XF_OFF + (it & 1) * 32768;
                float acc[2][8][4];
                #pragma unroll
                for (int mt = 0; mt < 2; ++mt)
                    #pragma unroll
                    for (int nt = 0; nt < 8; ++nt)
                        #pragma unroll
                        for (int k = 0; k < 4; ++k) acc[mt][nt][k] = 0.f;

                // pure-SMEM mainloop: 16 K-steps, no barriers, no cp.async
                #pragma unroll 4
                for (int s = 0; s < 16; ++s) {
                    const char* wfs = smem + WF_OFF + s * 8192;
                    const char* xfs = xfc + s * 2048;

                    uint4 A[2];
                    #pragma unroll
                    for (int mt = 0; mt < 2; ++mt) {
                        int mtg = warp_m * 2 + mt;
                        A[mt] = *reinterpret_cast<const uint4*>(xfs + (mtg * 32 + lane) * 16);
                    }
                    #pragma unroll
                    for (int i = 0; i < 4; ++i) {
                        uint4 B = *reinterpret_cast<const uint4*>(
                            wfs + ((warp_n * 4 + i) * 32 + lane) * 16);
                        mma16816(acc[0][i * 2 + 0], A[0], B.x, B.y);
                        mma16816(acc[1][i * 2 + 0], A[1], B.x, B.y);
                        mma16816(acc[0][i * 2 + 1], A[0], B.z, B.w);
                        mma16816(acc[1][i * 2 + 1], A[1], B.z, B.w);
                    }
                }

                // epilogue: p = sum_col relu(D+b1)*W2, quad-reduce
                {
                    const float2* wb = reinterpret_cast<const float2*>(smem + W2B1_OFF);
                    float* pred = reinterpret_cast<float*>(smem + PRED_OFF);
                    #pragma unroll
                    for (int mt = 0; mt < 2; ++mt) {
                        float p0 = 0.f, p1 = 0.f;
                        #pragma unroll
                        for (int nt = 0; nt < 8; ++nt) {
                            int col0 = warp_n * 64 + nt * 8 + q * 2;
                            float2 c0 = wb[col0];
                            float2 c1 = wb[col0 + 1];
                            const float* c = acc[mt][nt];
                            p0 = fmaf(fmaxf(c[0] + c0.x, 0.f), c0.y, p0);
                            p0 = fmaf(fmaxf(c[1] + c1.x, 0.f), c1.y, p0);
                            p1 = fmaf(fmaxf(c[2] + c0.x, 0.f), c0.y, p1);
                            p1 = fmaf(fmaxf(c[3] + c1.x, 0.f), c1.y, p1);
                        }
                        #pragma unroll
                        for (int off = 1; off < 4; off <<= 1) {
                            p0 += __shfl_xor_sync(0xffffffffu, p0, off);
                            p1 += __shfl_xor_sync(0xffffffffu, p1, off);
                        }
                        if (q == 0) {
                            int row = warp_m * 32 + mt * 16 + g;
                            pred[warp_n * 64 + row]     = p0;
                            pred[warp_n * 64 + row + 8] = p1;
                        }
                    }
                    CBAR();
                    if (t < 64) {
                        const float* pr = reinterpret_cast<const float*>(smem + PRED_OFF);
                        float ptot = pr[t] + pr[t + 64] + pr[t + 128] + pr[t + 192];
                        float sscore = fmaxf(ptot + b2v, 0.f) * invd_reg;
                        reinterpret_cast<float*>(smem + SC_OFF + (it & 1) * 256)[t] = sscore;
                    }
                }
            }
        } else {
            // ================= U-group: convert(it+1), softmax+phase5(it-1) =================
            const int ut = t - 256;
            if (it + 1 < T) {
                const int bsn = bid + (it + 1) * GRID;
                convert_x(reinterpret_cast<const float4*>(features + (size_t)bsn * (Lq * Fq)),
                          smem + XF_OFF + ((it + 1) & 1) * 32768, ut, 256, 16);
            }
            if (it >= 1) {
                const int bsp = bid + (it - 1) * GRID;
                if (wid == 8) {
                    const float* sc = reinterpret_cast<const float*>(smem + SC_OFF + ((it - 1) & 1) * 256);
                    float* wg = reinterpret_cast<float*>(smem + WGT_OFF);
                    float s0 = sc[lane], s1 = sc[lane + 32];
                    float m = fmaxf(s0, s1);
                    #pragma unroll
                    for (int off = 16; off > 0; off >>= 1)
                        m = fmaxf(m, __shfl_xor_sync(0xffffffffu, m, off));
                    float e0 = expf(s0 - m), e1 = expf(s1 - m);
                    float ssum = e0 + e1;
                    #pragma unroll
                    for (int off = 16; off > 0; off >>= 1)
                        ssum += __shfl_xor_sync(0xffffffffu, ssum, off);
                    float inv = 1.f / ssum;
                    wg[lane] = e0 * inv;
                    wg[lane + 32] = e1 * inv;
                }
                UBAR();
                {
                    const float* wg = reinterpret_cast<const float*>(smem + WGT_OFF);
                    const float4* fx = reinterpret_cast<const float4*>(features + (size_t)bsp * (Lq * Fq));
                    float4* p54 = reinterpret_cast<float4*>(smem + P5_OFF);
                    const int fb  = ut & 63;
                    const int sub = ut >> 6;      // 0..3 -> l in [sub*16, +16)
                    float4 o = make_float4(0.f, 0.f, 0.f, 0.f);
                    #pragma unroll 4
                    for (int i = 0; i < 16; ++i) {
                        int l = sub * 16 + i;
                        float w = wg[l];
                        float4 x = fx[l * 64 + fb];
                        o.x = fmaf(w, x.x, o.x);
                        o.y = fmaf(w, x.y, o.y);
                        o.z = fmaf(w, x.z, o.z);
                        o.w = fmaf(w, x.w, o.w);
                    }
                    p54[ut] = o;
                    UBAR();
                    if (ut < 64) {
                        float4 a0 = p54[ut], a1 = p54[ut + 64], a2 = p54[ut + 128], a3 = p54[ut + 192];
                        float4 o2;
                        o2.x = a0.x + a1.x + a2.x + a3.x;
                        o2.y = a0.y + a1.y + a2.y + a3.y;
                        o2.z = a0.z + a1.z + a2.z + a3.z;
                        o2.w = a0.w + a1.w + a2.w + a3.w;
                        reinterpret_cast<float4*>(out + (size_t)bsp * Fq)[ut] = o2;
                    }
                }
            }
        }
    }
}

extern "C" void kernel_launch(void* const* d_in, const int* in_sizes, int n_in,
                              void* d_out, int out_size)
{
    const float* features = (const float*)d_in[0];
    const float* src_locs = (const float*)d_in[1];
    const float* tar_locs = (const float*)d_in[2];
    const float* W1       = (const float*)d_in[3];
    const float* b1       = (const float*)d_in[4];
    const float* W2       = (const float*)d_in[5];
    const float* b2       = (const float*)d_in[6];
    float* out            = (float*)d_out;

    stage_w1_kernel<<<32, 256>>>(W1);

    cudaFuncSetAttribute(ida_ws_kernel,
                         cudaFuncAttributeMaxDynamicSharedMemorySize, SMEM_BYTES);
    ida_ws_kernel<<<GRID, 512, SMEM_BYTES>>>(
        features, src_locs, tar_locs, b1, W2, b2, out);
}